// round 14
// baseline (speedup 1.0000x reference)
#include <cuda_runtime.h>
#include <cuda_bf16.h>
#include <cstdint>

#define N_NODES 100000
#define N_EDGES 1600000
#define IN_F    512
#define OUT_F   64
#define QRT_E   (N_EDGES / 4)

// ---- scratch (__device__ globals) ------------------------------------------
__device__ float    g_h[(size_t)N_NODES * OUT_F];   // projected features
__device__ float    g_deg[N_NODES];                 // in-degree per dst node
// W pre-split, packed bf16 pairs along k: [kpair][n]
__device__ unsigned g_Bhi[(IN_F / 2) * OUT_F];
__device__ unsigned g_Blo[(IN_F / 2) * OUT_F];

// ---- bf16 split helpers ------------------------------------------------------
__device__ __forceinline__ void split_bf16(float x, __nv_bfloat16& hi, __nv_bfloat16& lo) {
    hi = __float2bfloat16_rn(x);
    lo = __float2bfloat16_rn(x - __bfloat162float(hi));
}
__device__ __forceinline__ unsigned pack_bf16(__nv_bfloat16 a, __nv_bfloat16 b) {
    unsigned short ua = *reinterpret_cast<unsigned short*>(&a);
    unsigned short ub = *reinterpret_cast<unsigned short*>(&b);
    return (unsigned)ua | ((unsigned)ub << 16);
}

__device__ __forceinline__ void mma16(float& d0, float& d1, float& d2, float& d3,
                                      unsigned a0, unsigned a1, unsigned a2, unsigned a3,
                                      unsigned b0, unsigned b1) {
    asm volatile("mma.sync.aligned.m16n8k16.row.col.f32.bf16.bf16.f32 "
                 "{%0,%1,%2,%3},{%4,%5,%6,%7},{%8,%9},{%0,%1,%2,%3};"
                 : "+f"(d0), "+f"(d1), "+f"(d2), "+f"(d3)
                 : "r"(a0), "r"(a1), "r"(a2), "r"(a3), "r"(b0), "r"(b1));
}

// ---------------------------------------------------------------------------
// 0) fused init: zero out + deg, pre-split W
// ---------------------------------------------------------------------------
__global__ void init_kernel(float4* __restrict__ out4, const float* __restrict__ W) {
    const int i = blockIdx.x * blockDim.x + threadIdx.x;
    if (i < N_NODES * OUT_F / 4) out4[i] = make_float4(0.f, 0.f, 0.f, 0.f);
    if (i < N_NODES) g_deg[i] = 0.0f;
    if (i < (IN_F / 2) * OUT_F) {
        const int kp = i >> 6;
        const int n  = i & 63;
        const float x0 = W[(size_t)(2 * kp)     * OUT_F + n];
        const float x1 = W[(size_t)(2 * kp + 1) * OUT_F + n];
        __nv_bfloat16 h0, l0, h1, l1;
        split_bf16(x0, h0, l0);
        split_bf16(x1, h1, l1);
        g_Bhi[i] = pack_bf16(h0, h1);
        g_Blo[i] = pack_bf16(l0, l1);
    }
}

// ---------------------------------------------------------------------------
// 1) GEMM half-N (bf16 tensor cores, 3xBF16), cols [n0, n0+32).
//    Block tile 128x32, 8 warps of 16x32, KC=32, A register prefetch (R11).
// ---------------------------------------------------------------------------
__global__ __launch_bounds__(256) void gemm_bf16_n32_kernel(
    const float* __restrict__ feat, const int n0)
{
    __shared__ unsigned As_hi[128][20];
    __shared__ unsigned As_lo[128][20];
    __shared__ unsigned Bs_hi[16][40];
    __shared__ unsigned Bs_lo[16][40];

    const int tid  = threadIdx.x;
    const int wid  = tid >> 5;      // 0..7 -> m slice of 16 rows
    const int lane = tid & 31;
    const int gid  = lane >> 2;     // 0..7
    const int tig  = lane & 3;      // 0..3
    const int m0   = blockIdx.x * 128;

    // A loader mapping: 4 float4 chunks per thread
    const int lr[4] = { (tid) >> 3, (tid + 256) >> 3, (tid + 512) >> 3, (tid + 768) >> 3 };
    const int lf    = tid & 7;
    // B loader mapping: threads 0..127 load 1 uint4 per array
    const int bkp = tid >> 3;           // 0..31 (only tid<128 -> 0..15)
    const int bn4 = (tid & 7) * 4;

    float acc[4][4] = {};
    float4 ra[4];

    // prologue: A tile 0
    #pragma unroll
    for (int q = 0; q < 4; q++) {
        ra[q] = make_float4(0.f, 0.f, 0.f, 0.f);
        if (m0 + lr[q] < N_NODES)
            ra[q] = *reinterpret_cast<const float4*>(feat + (size_t)(m0 + lr[q]) * IN_F + lf * 4);
    }

    for (int k0 = 0; k0 < IN_F; k0 += 32) {
        // split + store A
        #pragma unroll
        for (int q = 0; q < 4; q++) {
            __nv_bfloat16 hx, lx, hy, ly, hz, lz, hw, lw;
            split_bf16(ra[q].x, hx, lx); split_bf16(ra[q].y, hy, ly);
            split_bf16(ra[q].z, hz, lz); split_bf16(ra[q].w, hw, lw);
            As_hi[lr[q]][lf * 2]     = pack_bf16(hx, hy);
            As_hi[lr[q]][lf * 2 + 1] = pack_bf16(hz, hw);
            As_lo[lr[q]][lf * 2]     = pack_bf16(lx, ly);
            As_lo[lr[q]][lf * 2 + 1] = pack_bf16(lz, lw);
        }
        // B tile: 16 kpairs x 32 cols = 128 uint4 per array
        if (tid < 128) {
            const size_t gidx = (size_t)(k0 / 2 + bkp) * OUT_F + n0 + bn4;
            *reinterpret_cast<uint4*>(&Bs_hi[bkp][bn4]) = *reinterpret_cast<const uint4*>(g_Bhi + gidx);
            *reinterpret_cast<uint4*>(&Bs_lo[bkp][bn4]) = *reinterpret_cast<const uint4*>(g_Blo + gidx);
        }
        __syncthreads();

        // prefetch next A tile
        const int kn = k0 + 32;
        if (kn < IN_F) {
            #pragma unroll
            for (int q = 0; q < 4; q++) {
                ra[q] = make_float4(0.f, 0.f, 0.f, 0.f);
                if (m0 + lr[q] < N_NODES)
                    ra[q] = *reinterpret_cast<const float4*>(feat + (size_t)(m0 + lr[q]) * IN_F + kn + lf * 4);
            }
        }

        #pragma unroll
        for (int kf = 0; kf < 2; kf++) {
            const int pb = kf * 8;
            const int r = wid * 16 + gid;
            unsigned ah[4], al[4];
            ah[0] = As_hi[r][pb + tig];
            ah[1] = As_hi[r + 8][pb + tig];
            ah[2] = As_hi[r][pb + tig + 4];
            ah[3] = As_hi[r + 8][pb + tig + 4];
            al[0] = As_lo[r][pb + tig];
            al[1] = As_lo[r + 8][pb + tig];
            al[2] = As_lo[r][pb + tig + 4];
            al[3] = As_lo[r + 8][pb + tig + 4];
            #pragma unroll
            for (int nf = 0; nf < 4; nf++) {
                const int c = nf * 8 + gid;
                const unsigned bh0 = Bs_hi[pb + tig][c];
                const unsigned bh1 = Bs_hi[pb + tig + 4][c];
                const unsigned bl0 = Bs_lo[pb + tig][c];
                const unsigned bl1 = Bs_lo[pb + tig + 4][c];
                float* d = acc[nf];
                mma16(d[0], d[1], d[2], d[3], ah[0], ah[1], ah[2], ah[3], bh0, bh1);
                mma16(d[0], d[1], d[2], d[3], ah[0], ah[1], ah[2], ah[3], bl0, bl1);
                mma16(d[0], d[1], d[2], d[3], al[0], al[1], al[2], al[3], bh0, bh1);
            }
        }
        __syncthreads();
    }

    // epilogue
    #pragma unroll
    for (int nf = 0; nf < 4; nf++) {
        const int c  = n0 + nf * 8 + tig * 2;
        const int r0 = m0 + wid * 16 + gid;
        if (r0 < N_NODES)
            *reinterpret_cast<float2*>(g_h + (size_t)r0 * OUT_F + c) =
                make_float2(acc[nf][0], acc[nf][1]);
        if (r0 + 8 < N_NODES)
            *reinterpret_cast<float2*>(g_h + (size_t)(r0 + 8) * OUT_F + c) =
                make_float2(acc[nf][2], acc[nf][3]);
    }
}

// ---------------------------------------------------------------------------
// 2) Edge scatter half-N, MLP=4: 8 lanes per edge (cols [n0, n0+32)).
// ---------------------------------------------------------------------------
template <int DO_DEG>
__global__ __launch_bounds__(256) void edge_n32_kernel(
    const int* __restrict__ src, const int* __restrict__ dst,
    const float* __restrict__ ew, float* __restrict__ out, const int n0)
{
    const long long t = (long long)blockIdx.x * blockDim.x + threadIdx.x;
    const int e0 = (int)(t >> 3);
    const int l  = (int)(t & 7);
    if (e0 >= QRT_E) return;

    int   s[4], d[4];
    float w[4];
    #pragma unroll
    for (int q = 0; q < 4; q++) {
        const int e = e0 + q * QRT_E;
        s[q] = __ldg(src + e);
        d[q] = __ldg(dst + e);
        w[q] = __ldg(ew  + e);
    }

    float4 v[4];
    #pragma unroll
    for (int q = 0; q < 4; q++)
        v[q] = *reinterpret_cast<const float4*>(g_h + (size_t)s[q] * OUT_F + n0 + l * 4);

    #pragma unroll
    for (int q = 0; q < 4; q++) {
        v[q].x *= w[q]; v[q].y *= w[q]; v[q].z *= w[q]; v[q].w *= w[q];
        float* p = out + (size_t)d[q] * OUT_F + n0 + l * 4;
        asm volatile("red.global.add.v4.f32 [%0], {%1,%2,%3,%4};"
                     :: "l"(p), "f"(v[q].x), "f"(v[q].y), "f"(v[q].z), "f"(v[q].w)
                     : "memory");
    }

    if (DO_DEG && l == 0) {
        #pragma unroll
        for (int q = 0; q < 4; q++) atomicAdd(&g_deg[d[q]], 1.0f);
    }
}

// ---------------------------------------------------------------------------
// 3) finalize (vectorized): out = relu( msum * (deg>0 ? 1/deg : 0) + bias )
// ---------------------------------------------------------------------------
__global__ void finalize_kernel(float4* __restrict__ out4, const float* __restrict__ bias) {
    const int i = blockIdx.x * blockDim.x + threadIdx.x;
    if (i >= N_NODES * OUT_F / 4) return;
    const int node = i >> 4;
    const int c4   = (i & 15) * 4;
    const float d  = g_deg[node];
    const float rinv = (d > 0.0f) ? (1.0f / d) : 0.0f;
    float4 v = out4[i];
    v.x = fmaxf(fmaf(v.x, rinv, __ldg(bias + c4 + 0)), 0.0f);
    v.y = fmaxf(fmaf(v.y, rinv, __ldg(bias + c4 + 1)), 0.0f);
    v.z = fmaxf(fmaf(v.z, rinv, __ldg(bias + c4 + 2)), 0.0f);
    v.w = fmaxf(fmaf(v.w, rinv, __ldg(bias + c4 + 3)), 0.0f);
    out4[i] = v;
}

// ---------------------------------------------------------------------------
// Launch: fork/join pipeline
//   s1: init -> gemm(cols 0-31) -> edge(0-31, deg) ----------\
//   s2:            (after gemm1) gemm(cols 32-63) -> edge(32-63) -> join
//   s1: finalize (after both edges)
// ---------------------------------------------------------------------------
extern "C" void kernel_launch(void* const* d_in, const int* in_sizes, int n_in,
                              void* d_out, int out_size)
{
    const float* feat     = (const float*)d_in[0];
    const float* edge_w   = (const float*)d_in[1];
    const float* weight   = (const float*)d_in[2];
    const float* bias     = (const float*)d_in[3];
    const int*   edge_src = (const int*)d_in[4];
    const int*   edge_dst = (const int*)d_in[5];
    float* out = (float*)d_out;

    static cudaStream_t s1 = nullptr, s2 = nullptr;
    static cudaEvent_t evFork, evG1, evE2, evDone;
    if (s1 == nullptr) {
        cudaStreamCreateWithFlags(&s1, cudaStreamNonBlocking);
        cudaStreamCreateWithFlags(&s2, cudaStreamNonBlocking);
        cudaEventCreateWithFlags(&evFork, cudaEventDisableTiming);
        cudaEventCreateWithFlags(&evG1,   cudaEventDisableTiming);
        cudaEventCreateWithFlags(&evE2,   cudaEventDisableTiming);
        cudaEventCreateWithFlags(&evDone, cudaEventDisableTiming);
    }

    const int edge_blocks = (int)(((long long)QRT_E * 8 + 255) / 256);

    // fork from the (capturing) default stream
    cudaEventRecord(evFork, 0);
    cudaStreamWaitEvent(s1, evFork, 0);
    cudaStreamWaitEvent(s2, evFork, 0);

    // s1: init, first GEMM half, first edge half (with deg)
    init_kernel<<<(N_NODES * OUT_F / 4 + 255) / 256, 256, 0, s1>>>((float4*)out, weight);
    gemm_bf16_n32_kernel<<<(N_NODES + 127) / 128, 256, 0, s1>>>(feat, 0);
    cudaEventRecord(evG1, s1);
    edge_n32_kernel<1><<<edge_blocks, 256, 0, s1>>>(edge_src, edge_dst, edge_w, out, 0);

    // s2: second GEMM half (overlaps edge1), second edge half
    cudaStreamWaitEvent(s2, evG1, 0);
    gemm_bf16_n32_kernel<<<(N_NODES + 127) / 128, 256, 0, s2>>>(feat, 32);
    edge_n32_kernel<0><<<edge_blocks, 256, 0, s2>>>(edge_src, edge_dst, edge_w, out, 32);
    cudaEventRecord(evE2, s2);

    // s1: finalize after both edge halves
    cudaStreamWaitEvent(s1, evE2, 0);
    finalize_kernel<<<(N_NODES * OUT_F / 4 + 255) / 256, 256, 0, s1>>>((float4*)out, bias);
    cudaEventRecord(evDone, s1);

    // join back into the capture-origin stream
    cudaStreamWaitEvent(0, evDone, 0);
}

// round 15
// speedup vs baseline: 1.2133x; 1.2133x over previous
#include <cuda_runtime.h>
#include <cuda_bf16.h>
#include <cstdint>

#define N_NODES 100000
#define N_EDGES 1600000
#define IN_F    512
#define OUT_F   64
#define QRT_E   (N_EDGES / 4)

// ---- scratch (__device__ globals) ------------------------------------------
__device__ float    g_h[(size_t)N_NODES * OUT_F];   // projected features
__device__ float    g_deg[N_NODES];                 // in-degree per dst node
// W pre-split, packed bf16 pairs along k: [kpair][n]
__device__ unsigned g_Bhi[(IN_F / 2) * OUT_F];
__device__ unsigned g_Blo[(IN_F / 2) * OUT_F];

// ---- bf16 split helpers ------------------------------------------------------
__device__ __forceinline__ void split_bf16(float x, __nv_bfloat16& hi, __nv_bfloat16& lo) {
    hi = __float2bfloat16_rn(x);
    lo = __float2bfloat16_rn(x - __bfloat162float(hi));
}
__device__ __forceinline__ unsigned pack_bf16(__nv_bfloat16 a, __nv_bfloat16 b) {
    unsigned short ua = *reinterpret_cast<unsigned short*>(&a);
    unsigned short ub = *reinterpret_cast<unsigned short*>(&b);
    return (unsigned)ua | ((unsigned)ub << 16);
}

__device__ __forceinline__ void mma16(float& d0, float& d1, float& d2, float& d3,
                                      unsigned a0, unsigned a1, unsigned a2, unsigned a3,
                                      unsigned b0, unsigned b1) {
    asm volatile("mma.sync.aligned.m16n8k16.row.col.f32.bf16.bf16.f32 "
                 "{%0,%1,%2,%3},{%4,%5,%6,%7},{%8,%9},{%0,%1,%2,%3};"
                 : "+f"(d0), "+f"(d1), "+f"(d2), "+f"(d3)
                 : "r"(a0), "r"(a1), "r"(a2), "r"(a3), "r"(b0), "r"(b1));
}

// ---------------------------------------------------------------------------
// 0) fused init: zero out + deg, pre-split W
// ---------------------------------------------------------------------------
__global__ void init_kernel(float4* __restrict__ out4, const float* __restrict__ W) {
    const int i = blockIdx.x * blockDim.x + threadIdx.x;
    if (i < N_NODES * OUT_F / 4) out4[i] = make_float4(0.f, 0.f, 0.f, 0.f);
    if (i < N_NODES) g_deg[i] = 0.0f;
    if (i < (IN_F / 2) * OUT_F) {
        const int kp = i >> 6;
        const int n  = i & 63;
        const float x0 = W[(size_t)(2 * kp)     * OUT_F + n];
        const float x1 = W[(size_t)(2 * kp + 1) * OUT_F + n];
        __nv_bfloat16 h0, l0, h1, l1;
        split_bf16(x0, h0, l0);
        split_bf16(x1, h1, l1);
        g_Bhi[i] = pack_bf16(h0, h1);
        g_Blo[i] = pack_bf16(l0, l1);
    }
}

// ---------------------------------------------------------------------------
// 1) GEMM (bf16 tensor cores, 3xBF16), block tile 64x64 for HIGH OCCUPANCY.
//    8 warps (4m x 2n), warp tile 16x32, KC=32 (2 x k16), A register prefetch.
// ---------------------------------------------------------------------------
__global__ void __launch_bounds__(256, 4) gemm_bf16_kernel(
    const float* __restrict__ feat)
{
    __shared__ unsigned As_hi[64][20];
    __shared__ unsigned As_lo[64][20];
    __shared__ unsigned Bs_hi[16][72];
    __shared__ unsigned Bs_lo[16][72];

    const int tid  = threadIdx.x;
    const int wid  = tid >> 5;
    const int lane = tid & 31;
    const int wm   = wid >> 1;      // 0..3 (m: 4 x 16)
    const int wn   = wid & 1;       // 0..1 (n: 2 x 32)
    const int gid  = lane >> 2;     // 0..7
    const int tig  = lane & 3;      // 0..3
    const int m0   = blockIdx.x * 64;

    // A loader mapping: 64 rows x 8 float4 = 512 float4, 2 per thread
    const int lr0 = tid >> 3;
    const int lr1 = (tid + 256) >> 3;
    const int lf  = tid & 7;
    // B loader mapping: 1 uint4 per thread per array
    const int bkp = tid >> 4;
    const int bn4 = (tid & 15) * 4;

    float acc[4][4] = {};
    float4 ra0, ra1;

    // prologue: A tile 0
    ra0 = make_float4(0.f, 0.f, 0.f, 0.f);
    ra1 = make_float4(0.f, 0.f, 0.f, 0.f);
    if (m0 + lr0 < N_NODES)
        ra0 = *reinterpret_cast<const float4*>(feat + (size_t)(m0 + lr0) * IN_F + lf * 4);
    if (m0 + lr1 < N_NODES)
        ra1 = *reinterpret_cast<const float4*>(feat + (size_t)(m0 + lr1) * IN_F + lf * 4);

    for (int k0 = 0; k0 < IN_F; k0 += 32) {
        // split + store A
        {
            __nv_bfloat16 hx, lx, hy, ly, hz, lz, hw, lw;
            split_bf16(ra0.x, hx, lx); split_bf16(ra0.y, hy, ly);
            split_bf16(ra0.z, hz, lz); split_bf16(ra0.w, hw, lw);
            As_hi[lr0][lf * 2]     = pack_bf16(hx, hy);
            As_hi[lr0][lf * 2 + 1] = pack_bf16(hz, hw);
            As_lo[lr0][lf * 2]     = pack_bf16(lx, ly);
            As_lo[lr0][lf * 2 + 1] = pack_bf16(lz, lw);
            split_bf16(ra1.x, hx, lx); split_bf16(ra1.y, hy, ly);
            split_bf16(ra1.z, hz, lz); split_bf16(ra1.w, hw, lw);
            As_hi[lr1][lf * 2]     = pack_bf16(hx, hy);
            As_hi[lr1][lf * 2 + 1] = pack_bf16(hz, hw);
            As_lo[lr1][lf * 2]     = pack_bf16(lx, ly);
            As_lo[lr1][lf * 2 + 1] = pack_bf16(lz, lw);
        }
        // B tile: 16 kpairs x 64 n = 256 uint4 per array (1 per thread)
        {
            const size_t gidx = (size_t)(k0 / 2 + bkp) * OUT_F + bn4;
            *reinterpret_cast<uint4*>(&Bs_hi[bkp][bn4]) = *reinterpret_cast<const uint4*>(g_Bhi + gidx);
            *reinterpret_cast<uint4*>(&Bs_lo[bkp][bn4]) = *reinterpret_cast<const uint4*>(g_Blo + gidx);
        }
        __syncthreads();

        // prefetch next A tile (overlaps MMAs)
        const int kn = k0 + 32;
        if (kn < IN_F) {
            ra0 = make_float4(0.f, 0.f, 0.f, 0.f);
            ra1 = make_float4(0.f, 0.f, 0.f, 0.f);
            if (m0 + lr0 < N_NODES)
                ra0 = *reinterpret_cast<const float4*>(feat + (size_t)(m0 + lr0) * IN_F + kn + lf * 4);
            if (m0 + lr1 < N_NODES)
                ra1 = *reinterpret_cast<const float4*>(feat + (size_t)(m0 + lr1) * IN_F + kn + lf * 4);
        }

        #pragma unroll
        for (int kf = 0; kf < 2; kf++) {
            const int pb = kf * 8;
            const int r  = wm * 16 + gid;
            unsigned ah[4], al[4];
            ah[0] = As_hi[r][pb + tig];
            ah[1] = As_hi[r + 8][pb + tig];
            ah[2] = As_hi[r][pb + tig + 4];
            ah[3] = As_hi[r + 8][pb + tig + 4];
            al[0] = As_lo[r][pb + tig];
            al[1] = As_lo[r + 8][pb + tig];
            al[2] = As_lo[r][pb + tig + 4];
            al[3] = As_lo[r + 8][pb + tig + 4];
            #pragma unroll
            for (int nf = 0; nf < 4; nf++) {
                const int c = wn * 32 + nf * 8 + gid;
                const unsigned bh0 = Bs_hi[pb + tig][c];
                const unsigned bh1 = Bs_hi[pb + tig + 4][c];
                const unsigned bl0 = Bs_lo[pb + tig][c];
                const unsigned bl1 = Bs_lo[pb + tig + 4][c];
                float* d = acc[nf];
                mma16(d[0], d[1], d[2], d[3], ah[0], ah[1], ah[2], ah[3], bh0, bh1);
                mma16(d[0], d[1], d[2], d[3], ah[0], ah[1], ah[2], ah[3], bl0, bl1);
                mma16(d[0], d[1], d[2], d[3], al[0], al[1], al[2], al[3], bh0, bh1);
            }
        }
        __syncthreads();
    }

    // epilogue
    #pragma unroll
    for (int nf = 0; nf < 4; nf++) {
        const int c  = wn * 32 + nf * 8 + tig * 2;
        const int r0 = m0 + wm * 16 + gid;
        if (r0 < N_NODES)
            *reinterpret_cast<float2*>(g_h + (size_t)r0 * OUT_F + c) =
                make_float2(acc[nf][0], acc[nf][1]);
        if (r0 + 8 < N_NODES)
            *reinterpret_cast<float2*>(g_h + (size_t)(r0 + 8) * OUT_F + c) =
                make_float2(acc[nf][2], acc[nf][3]);
    }
}

// ---------------------------------------------------------------------------
// 2) Edge scatter, MLP=4 (unchanged from R11)
// ---------------------------------------------------------------------------
__global__ __launch_bounds__(256) void edge_kernel(
    const int* __restrict__ src, const int* __restrict__ dst,
    const float* __restrict__ ew, float* __restrict__ out)
{
    const long long t = (long long)blockIdx.x * blockDim.x + threadIdx.x;
    const int e0 = (int)(t >> 4);
    const int l  = (int)(t & 15);
    if (e0 >= QRT_E) return;

    int   s[4], d[4];
    float w[4];
    #pragma unroll
    for (int q = 0; q < 4; q++) {
        const int e = e0 + q * QRT_E;
        s[q] = __ldg(src + e);
        d[q] = __ldg(dst + e);
        w[q] = __ldg(ew  + e);
    }

    float4 v[4];
    #pragma unroll
    for (int q = 0; q < 4; q++)
        v[q] = *reinterpret_cast<const float4*>(g_h + (size_t)s[q] * OUT_F + l * 4);

    #pragma unroll
    for (int q = 0; q < 4; q++) {
        v[q].x *= w[q]; v[q].y *= w[q]; v[q].z *= w[q]; v[q].w *= w[q];
        float* p = out + (size_t)d[q] * OUT_F + l * 4;
        asm volatile("red.global.add.v4.f32 [%0], {%1,%2,%3,%4};"
                     :: "l"(p), "f"(v[q].x), "f"(v[q].y), "f"(v[q].z), "f"(v[q].w)
                     : "memory");
    }

    if (l == 0) {
        #pragma unroll
        for (int q = 0; q < 4; q++) atomicAdd(&g_deg[d[q]], 1.0f);
    }
}

// ---------------------------------------------------------------------------
// 3) finalize (vectorized): out = relu( msum * (deg>0 ? 1/deg : 0) + bias )
// ---------------------------------------------------------------------------
__global__ void finalize_kernel(float4* __restrict__ out4, const float* __restrict__ bias) {
    const int i = blockIdx.x * blockDim.x + threadIdx.x;
    if (i >= N_NODES * OUT_F / 4) return;
    const int node = i >> 4;
    const int c4   = (i & 15) * 4;
    const float d  = g_deg[node];
    const float rinv = (d > 0.0f) ? (1.0f / d) : 0.0f;
    float4 v = out4[i];
    v.x = fmaxf(fmaf(v.x, rinv, __ldg(bias + c4 + 0)), 0.0f);
    v.y = fmaxf(fmaf(v.y, rinv, __ldg(bias + c4 + 1)), 0.0f);
    v.z = fmaxf(fmaf(v.z, rinv, __ldg(bias + c4 + 2)), 0.0f);
    v.w = fmaxf(fmaf(v.w, rinv, __ldg(bias + c4 + 3)), 0.0f);
    out4[i] = v;
}

// ---------------------------------------------------------------------------
extern "C" void kernel_launch(void* const* d_in, const int* in_sizes, int n_in,
                              void* d_out, int out_size)
{
    const float* feat     = (const float*)d_in[0];
    const float* edge_w   = (const float*)d_in[1];
    const float* weight   = (const float*)d_in[2];
    const float* bias     = (const float*)d_in[3];
    const int*   edge_src = (const int*)d_in[4];
    const int*   edge_dst = (const int*)d_in[5];
    float* out = (float*)d_out;

    init_kernel<<<(N_NODES * OUT_F / 4 + 255) / 256, 256>>>((float4*)out, weight);
    gemm_bf16_kernel<<<(N_NODES + 63) / 64, 256>>>(feat);
    edge_kernel<<<(int)(((long long)QRT_E * 16 + 255) / 256), 256>>>(edge_src, edge_dst, edge_w, out);
    finalize_kernel<<<(N_NODES * OUT_F / 4 + 255) / 256, 256>>>((float4*)out, bias);
}

// round 16
// speedup vs baseline: 1.2335x; 1.0166x over previous
#include <cuda_runtime.h>
#include <cuda_bf16.h>
#include <cstdint>

#define N_NODES 100000
#define N_EDGES 1600000
#define IN_F    512
#define OUT_F   64
#define QRT_E   (N_EDGES / 4)

// ---- scratch (__device__ globals) ------------------------------------------
__device__ float    g_h[(size_t)N_NODES * OUT_F];   // projected features
__device__ float    g_deg[N_NODES];                 // in-degree per dst node
// W pre-split, packed bf16 pairs along k: [kpair][n]
__device__ unsigned g_Bhi[(IN_F / 2) * OUT_F];
__device__ unsigned g_Blo[(IN_F / 2) * OUT_F];

// ---- bf16 split helpers ------------------------------------------------------
__device__ __forceinline__ void split_bf16(float x, __nv_bfloat16& hi, __nv_bfloat16& lo) {
    hi = __float2bfloat16_rn(x);
    lo = __float2bfloat16_rn(x - __bfloat162float(hi));
}
__device__ __forceinline__ unsigned pack_bf16(__nv_bfloat16 a, __nv_bfloat16 b) {
    unsigned short ua = *reinterpret_cast<unsigned short*>(&a);
    unsigned short ub = *reinterpret_cast<unsigned short*>(&b);
    return (unsigned)ua | ((unsigned)ub << 16);
}

__device__ __forceinline__ void mma16(float& d0, float& d1, float& d2, float& d3,
                                      unsigned a0, unsigned a1, unsigned a2, unsigned a3,
                                      unsigned b0, unsigned b1) {
    asm volatile("mma.sync.aligned.m16n8k16.row.col.f32.bf16.bf16.f32 "
                 "{%0,%1,%2,%3},{%4,%5,%6,%7},{%8,%9},{%0,%1,%2,%3};"
                 : "+f"(d0), "+f"(d1), "+f"(d2), "+f"(d3)
                 : "r"(a0), "r"(a1), "r"(a2), "r"(a3), "r"(b0), "r"(b1));
}

// L1-bypassing v4 gather (random rows of g_h never re-hit L1)
__device__ __forceinline__ float4 ldg_na_v4(const float* p) {
    float4 v;
    asm volatile("ld.global.nc.L1::no_allocate.v4.f32 {%0,%1,%2,%3}, [%4];"
                 : "=f"(v.x), "=f"(v.y), "=f"(v.z), "=f"(v.w) : "l"(p));
    return v;
}

// ---------------------------------------------------------------------------
// 0) fused init: zero out + deg, pre-split W
// ---------------------------------------------------------------------------
__global__ void init_kernel(float4* __restrict__ out4, const float* __restrict__ W) {
    const int i = blockIdx.x * blockDim.x + threadIdx.x;
    if (i < N_NODES * OUT_F / 4) out4[i] = make_float4(0.f, 0.f, 0.f, 0.f);
    if (i < N_NODES) g_deg[i] = 0.0f;
    if (i < (IN_F / 2) * OUT_F) {
        const int kp = i >> 6;
        const int n  = i & 63;
        const float x0 = W[(size_t)(2 * kp)     * OUT_F + n];
        const float x1 = W[(size_t)(2 * kp + 1) * OUT_F + n];
        __nv_bfloat16 h0, l0, h1, l1;
        split_bf16(x0, h0, l0);
        split_bf16(x1, h1, l1);
        g_Bhi[i] = pack_bf16(h0, h1);
        g_Blo[i] = pack_bf16(l0, l1);
    }
}

// ---------------------------------------------------------------------------
// 1) GEMM (bf16 tensor cores, 3xBF16), R11 structure, 3 CTAs/SM target.
//    Block 128x64, 8 warps (4m x 2n), warp tile 32x32, KC=32, A reg prefetch.
// ---------------------------------------------------------------------------
__global__ void __launch_bounds__(256, 3) gemm_bf16_kernel(
    const float* __restrict__ feat)
{
    __shared__ unsigned As_hi[128][20];
    __shared__ unsigned As_lo[128][20];
    __shared__ unsigned Bs_hi[16][72];
    __shared__ unsigned Bs_lo[16][72];

    const int tid  = threadIdx.x;
    const int wid  = tid >> 5;
    const int lane = tid & 31;
    const int wm   = wid >> 1;
    const int wn   = wid & 1;
    const int gid  = lane >> 2;
    const int tig  = lane & 3;
    const int m0   = blockIdx.x * 128;

    // A loader mapping: 4 float4 chunks per thread
    const int lr[4] = { (tid) >> 3, (tid + 256) >> 3, (tid + 512) >> 3, (tid + 768) >> 3 };
    const int lf    = tid & 7;
    // B loader mapping: 1 uint4 per thread per array
    const int bkp = tid >> 4;
    const int bn4 = (tid & 15) * 4;

    float acc[2][4][4] = {};
    float4 ra[4];

    // prologue: A tile 0
    #pragma unroll
    for (int q = 0; q < 4; q++) {
        ra[q] = make_float4(0.f, 0.f, 0.f, 0.f);
        if (m0 + lr[q] < N_NODES)
            ra[q] = *reinterpret_cast<const float4*>(feat + (size_t)(m0 + lr[q]) * IN_F + lf * 4);
    }

    for (int k0 = 0; k0 < IN_F; k0 += 32) {
        // split + store A
        #pragma unroll
        for (int q = 0; q < 4; q++) {
            __nv_bfloat16 hx, lx, hy, ly, hz, lz, hw, lw;
            split_bf16(ra[q].x, hx, lx); split_bf16(ra[q].y, hy, ly);
            split_bf16(ra[q].z, hz, lz); split_bf16(ra[q].w, hw, lw);
            As_hi[lr[q]][lf * 2]     = pack_bf16(hx, hy);
            As_hi[lr[q]][lf * 2 + 1] = pack_bf16(hz, hw);
            As_lo[lr[q]][lf * 2]     = pack_bf16(lx, ly);
            As_lo[lr[q]][lf * 2 + 1] = pack_bf16(lz, lw);
        }
        // B tile
        {
            const size_t gidx = (size_t)(k0 / 2 + bkp) * OUT_F + bn4;
            *reinterpret_cast<uint4*>(&Bs_hi[bkp][bn4]) = *reinterpret_cast<const uint4*>(g_Bhi + gidx);
            *reinterpret_cast<uint4*>(&Bs_lo[bkp][bn4]) = *reinterpret_cast<const uint4*>(g_Blo + gidx);
        }
        __syncthreads();

        // prefetch next A tile
        const int kn = k0 + 32;
        if (kn < IN_F) {
            #pragma unroll
            for (int q = 0; q < 4; q++) {
                ra[q] = make_float4(0.f, 0.f, 0.f, 0.f);
                if (m0 + lr[q] < N_NODES)
                    ra[q] = *reinterpret_cast<const float4*>(feat + (size_t)(m0 + lr[q]) * IN_F + kn + lf * 4);
            }
        }

        #pragma unroll
        for (int kf = 0; kf < 2; kf++) {
            const int pb = kf * 8;
            unsigned ah[2][4], al[2][4];
            #pragma unroll
            for (int mf = 0; mf < 2; mf++) {
                const int r = wm * 32 + mf * 16 + gid;
                ah[mf][0] = As_hi[r][pb + tig];
                ah[mf][1] = As_hi[r + 8][pb + tig];
                ah[mf][2] = As_hi[r][pb + tig + 4];
                ah[mf][3] = As_hi[r + 8][pb + tig + 4];
                al[mf][0] = As_lo[r][pb + tig];
                al[mf][1] = As_lo[r + 8][pb + tig];
                al[mf][2] = As_lo[r][pb + tig + 4];
                al[mf][3] = As_lo[r + 8][pb + tig + 4];
            }
            unsigned bh[4][2], bl[4][2];
            #pragma unroll
            for (int nf = 0; nf < 4; nf++) {
                const int c = wn * 32 + nf * 8 + gid;
                bh[nf][0] = Bs_hi[pb + tig][c];
                bh[nf][1] = Bs_hi[pb + tig + 4][c];
                bl[nf][0] = Bs_lo[pb + tig][c];
                bl[nf][1] = Bs_lo[pb + tig + 4][c];
            }
            #pragma unroll
            for (int mf = 0; mf < 2; mf++)
                #pragma unroll
                for (int nf = 0; nf < 4; nf++) {
                    float* d = acc[mf][nf];
                    mma16(d[0], d[1], d[2], d[3],
                          ah[mf][0], ah[mf][1], ah[mf][2], ah[mf][3],
                          bh[nf][0], bh[nf][1]);
                    mma16(d[0], d[1], d[2], d[3],
                          ah[mf][0], ah[mf][1], ah[mf][2], ah[mf][3],
                          bl[nf][0], bl[nf][1]);
                    mma16(d[0], d[1], d[2], d[3],
                          al[mf][0], al[mf][1], al[mf][2], al[mf][3],
                          bh[nf][0], bh[nf][1]);
                }
        }
        __syncthreads();
    }

    #pragma unroll
    for (int mf = 0; mf < 2; mf++) {
        #pragma unroll
        for (int nf = 0; nf < 4; nf++) {
            const int c  = wn * 32 + nf * 8 + tig * 2;
            const int r0 = m0 + wm * 32 + mf * 16 + gid;
            if (r0 < N_NODES)
                *reinterpret_cast<float2*>(g_h + (size_t)r0 * OUT_F + c) =
                    make_float2(acc[mf][nf][0], acc[mf][nf][1]);
            if (r0 + 8 < N_NODES)
                *reinterpret_cast<float2*>(g_h + (size_t)(r0 + 8) * OUT_F + c) =
                    make_float2(acc[mf][nf][2], acc[mf][nf][3]);
        }
    }
}

// ---------------------------------------------------------------------------
// 2) Edge scatter, MLP=4, L1-bypassing gathers
// ---------------------------------------------------------------------------
__global__ __launch_bounds__(256) void edge_kernel(
    const int* __restrict__ src, const int* __restrict__ dst,
    const float* __restrict__ ew, float* __restrict__ out)
{
    const long long t = (long long)blockIdx.x * blockDim.x + threadIdx.x;
    const int e0 = (int)(t >> 4);
    const int l  = (int)(t & 15);
    if (e0 >= QRT_E) return;

    int   s[4], d[4];
    float w[4];
    #pragma unroll
    for (int q = 0; q < 4; q++) {
        const int e = e0 + q * QRT_E;
        s[q] = __ldg(src + e);
        d[q] = __ldg(dst + e);
        w[q] = __ldg(ew  + e);
    }

    float4 v[4];
    #pragma unroll
    for (int q = 0; q < 4; q++)
        v[q] = ldg_na_v4(g_h + (size_t)s[q] * OUT_F + l * 4);

    #pragma unroll
    for (int q = 0; q < 4; q++) {
        v[q].x *= w[q]; v[q].y *= w[q]; v[q].z *= w[q]; v[q].w *= w[q];
        float* p = out + (size_t)d[q] * OUT_F + l * 4;
        asm volatile("red.global.add.v4.f32 [%0], {%1,%2,%3,%4};"
                     :: "l"(p), "f"(v[q].x), "f"(v[q].y), "f"(v[q].z), "f"(v[q].w)
                     : "memory");
    }

    if (l == 0) {
        #pragma unroll
        for (int q = 0; q < 4; q++) atomicAdd(&g_deg[d[q]], 1.0f);
    }
}

// ---------------------------------------------------------------------------
// 3) finalize (vectorized): out = relu( msum * (deg>0 ? 1/deg : 0) + bias )
// ---------------------------------------------------------------------------
__global__ void finalize_kernel(float4* __restrict__ out4, const float* __restrict__ bias) {
    const int i = blockIdx.x * blockDim.x + threadIdx.x;
    if (i >= N_NODES * OUT_F / 4) return;
    const int node = i >> 4;
    const int c4   = (i & 15) * 4;
    const float d  = g_deg[node];
    const float rinv = (d > 0.0f) ? (1.0f / d) : 0.0f;
    float4 v = out4[i];
    v.x = fmaxf(fmaf(v.x, rinv, __ldg(bias + c4 + 0)), 0.0f);
    v.y = fmaxf(fmaf(v.y, rinv, __ldg(bias + c4 + 1)), 0.0f);
    v.z = fmaxf(fmaf(v.z, rinv, __ldg(bias + c4 + 2)), 0.0f);
    v.w = fmaxf(fmaf(v.w, rinv, __ldg(bias + c4 + 3)), 0.0f);
    out4[i] = v;
}

// ---------------------------------------------------------------------------
extern "C" void kernel_launch(void* const* d_in, const int* in_sizes, int n_in,
                              void* d_out, int out_size)
{
    const float* feat     = (const float*)d_in[0];
    const float* edge_w   = (const float*)d_in[1];
    const float* weight   = (const float*)d_in[2];
    const float* bias     = (const float*)d_in[3];
    const int*   edge_src = (const int*)d_in[4];
    const int*   edge_dst = (const int*)d_in[5];
    float* out = (float*)d_out;

    init_kernel<<<(N_NODES * OUT_F / 4 + 255) / 256, 256>>>((float4*)out, weight);
    gemm_bf16_kernel<<<(N_NODES + 127) / 128, 256>>>(feat);
    edge_kernel<<<(int)(((long long)QRT_E * 16 + 255) / 256), 256>>>(edge_src, edge_dst, edge_w, out);
    finalize_kernel<<<(N_NODES * OUT_F / 4 + 255) / 256, 256>>>((float4*)out, bias);
}